// round 11
// baseline (speedup 1.0000x reference)
#include <cuda_runtime.h>
#include <cuda_bf16.h>
#include <cstdint>

#define N_NODES 8192
#define F_INP   512
#define H_DIM   256
#define D_DIM   64
#define N_EDGES 262144

typedef unsigned long long ull;

// ---------------- device scratch ---------------------------------------------
__device__ float g_hpre[N_NODES * H_DIM];
__device__ float g_h   [N_NODES * H_DIM];
__device__ float g_zpre[N_NODES * D_DIM];
__device__ int   g_cnt   [N_NODES];        // zero-init at load; re-zeroed by scatter
__device__ int   g_rowptr[N_NODES + 1];
__device__ int   g_fill  [N_NODES];
__device__ int   g_ecol  [N_EDGES];
__device__ float g_eval  [N_EDGES];

// ---------------- packed f32x2 helpers ---------------------------------------
__device__ __forceinline__ void ffma2(ull& acc, ull a, ull b) {
    asm("fma.rn.f32x2 %0, %1, %2, %0;" : "+l"(acc) : "l"(a), "l"(b));
}
__device__ __forceinline__ void addf32x2(ull& a, ull b) {
    asm("add.rn.f32x2 %0, %0, %1;" : "+l"(a) : "l"(b));
}
__device__ __forceinline__ ull pack2(float v) {
    ull r;
    asm("mov.b64 %0, {%1, %1};" : "=l"(r) : "f"(v));
    return r;
}
__device__ __forceinline__ void unpack2(ull v, float& lo, float& hi) {
    asm("mov.b64 {%0, %1}, %2;" : "=f"(lo), "=f"(hi) : "l"(v));
}
__device__ __forceinline__ float fast_sigmoid(float x) {
    return __fdividef(1.0f, 1.0f + __expf(-x));
}

// ============================ CSR build =======================================
__global__ void count_kernel(const int* __restrict__ rows) {
    int e = blockIdx.x * blockDim.x + threadIdx.x;
    if (e < N_EDGES) atomicAdd(&g_cnt[rows[e]], 1);
}

__global__ void scan_kernel() {
    __shared__ int sm[1024];
    int tid  = threadIdx.x;
    int base = tid * 8;
    int v[8], pre[8];
    int s = 0;
    #pragma unroll
    for (int i = 0; i < 8; i++) { v[i] = g_cnt[base + i]; pre[i] = s; s += v[i]; }
    sm[tid] = s;
    __syncthreads();
    for (int off = 1; off < 1024; off <<= 1) {
        int t = (tid >= off) ? sm[tid - off] : 0;
        __syncthreads();
        sm[tid] += t;
        __syncthreads();
    }
    int excl = sm[tid] - s;
    #pragma unroll
    for (int i = 0; i < 8; i++) {
        int p = excl + pre[i];
        g_rowptr[base + i] = p;
        g_fill[base + i]   = p;
    }
    if (tid == 1023) g_rowptr[N_NODES] = sm[1023];
}

__global__ void scatter_kernel(const int* __restrict__ rows,
                               const int* __restrict__ cols,
                               const float* __restrict__ vals) {
    int e = blockIdx.x * blockDim.x + threadIdx.x;
    if (e < N_EDGES) {
        int pos = atomicAdd(&g_fill[rows[e]], 1);
        g_ecol[pos] = cols[e];
        g_eval[pos] = vals[e];
    }
    if (e < N_NODES) g_cnt[e] = 0;
}

// ============================ gemm1: block-split-K ============================
// hpre = x @ W1 + b1.  [8192,256], K=512. 64x64 tile, TM=TN=8 (balanced),
// 128 threads: group 0 -> K[0:256), group 1 -> K[256:512); f32x2 reduction.
__global__ void __launch_bounds__(128)
gemm1_bsk_kernel(const float* __restrict__ A, const float* __restrict__ B,
                 const float* __restrict__ bias, float* __restrict__ C) {
    constexpr int BM = 64, BN = 64, BK = 16;
    constexpr int SA = BM + 4, SB = BN + 4;
    constexpr int GSZ = 4352;                 // floats per group region
    __shared__ float sm_all[2 * GSZ];         // [grp][As(2 buf) | Bs(2 buf)]

    const int row0 = blockIdx.y * BM;
    const int col0 = blockIdx.x * BN;
    const int tid  = threadIdx.x;
    const int grp  = tid >> 6;
    const int gt   = tid & 63;
    const int tx   = gt & 7;
    const int ty   = gt >> 3;
    const int kbase = grp * (F_INP / 2);

    float* Asg = sm_all + grp * GSZ;               // [2][BK*SA]
    float* Bsg = sm_all + grp * GSZ + 2 * BK * SA; // [2][BK*SB]

    float4 areg[4], breg[4];

    auto ldg_tile = [&](int k0) {
        #pragma unroll
        for (int v = 0; v < 4; v++) {
            int q = gt + v * 64;
            int r = q >> 2, kq = q & 3;                    // BK/4 = 4
            areg[v] = *(const float4*)&A[(size_t)(row0 + r) * F_INP + kbase + k0 + kq * 4];
        }
        #pragma unroll
        for (int v = 0; v < 4; v++) {
            int q = gt + v * 64;
            int k = q >> 4, cq = q & 15;                   // BN/4 = 16
            breg[v] = *(const float4*)&B[(size_t)(kbase + k0 + k) * H_DIM + col0 + cq * 4];
        }
    };
    auto sts_tile = [&](int buf) {
        #pragma unroll
        for (int v = 0; v < 4; v++) {
            int q = gt + v * 64;
            int r = q >> 2, kq = q & 3;
            Asg[buf * BK * SA + (kq * 4 + 0) * SA + r] = areg[v].x;
            Asg[buf * BK * SA + (kq * 4 + 1) * SA + r] = areg[v].y;
            Asg[buf * BK * SA + (kq * 4 + 2) * SA + r] = areg[v].z;
            Asg[buf * BK * SA + (kq * 4 + 3) * SA + r] = areg[v].w;
        }
        #pragma unroll
        for (int v = 0; v < 4; v++) {
            int q = gt + v * 64;
            int k = q >> 4, cq = q & 15;
            *(float4*)&Bsg[buf * BK * SB + k * SB + cq * 4] = breg[v];
        }
    };

    ull acc[8][4];
    #pragma unroll
    for (int i = 0; i < 8; i++)
        #pragma unroll
        for (int j = 0; j < 4; j++) acc[i][j] = 0ULL;

    ldg_tile(0);
    sts_tile(0);
    __syncthreads();

    const int T = (F_INP / 2) / BK;    // 16
    for (int t = 0; t < T; t++) {
        if (t + 1 < T) ldg_tile((t + 1) * BK);
        const int buf = t & 1;
        #pragma unroll
        for (int kk = 0; kk < BK; kk++) {
            float a_s[8];
            #pragma unroll
            for (int i = 0; i < 8; i += 4) {
                float4 av = *(const float4*)&Asg[buf * BK * SA + kk * SA + ty * 8 + i];
                a_s[i] = av.x; a_s[i + 1] = av.y; a_s[i + 2] = av.z; a_s[i + 3] = av.w;
            }
            ull b[4];
            #pragma unroll
            for (int j = 0; j < 8; j += 4) {
                ulonglong2 p = *(const ulonglong2*)&Bsg[buf * BK * SB + kk * SB + tx * 8 + j];
                b[j / 2] = p.x; b[j / 2 + 1] = p.y;
            }
            #pragma unroll
            for (int i = 0; i < 8; i++) {
                ull av2 = pack2(a_s[i]);
                #pragma unroll
                for (int j = 0; j < 4; j++)
                    ffma2(acc[i][j], av2, b[j]);
            }
        }
        if (t + 1 < T) {
            sts_tile((t + 1) & 1);
            __syncthreads();
        }
    }

    // reduce group 1 into group 0 via smem stage (group-1 region, 2048 ull)
    __syncthreads();
    ull* stg = (ull*)(sm_all + GSZ);
    if (grp == 1) {
        #pragma unroll
        for (int i = 0; i < 8; i++)
            #pragma unroll
            for (int j = 0; j < 4; j++)
                stg[gt * 32 + i * 4 + j] = acc[i][j];
    }
    __syncthreads();
    if (grp == 0) {
        #pragma unroll
        for (int i = 0; i < 8; i++) {
            size_t row = (size_t)(row0 + ty * 8 + i);
            #pragma unroll
            for (int j = 0; j < 4; j++) {
                addf32x2(acc[i][j], stg[gt * 32 + i * 4 + j]);
                float lo, hi;
                unpack2(acc[i][j], lo, hi);
                int c = col0 + tx * 8 + j * 2;
                float2 o = make_float2(lo + __ldg(&bias[c]), hi + __ldg(&bias[c + 1]));
                *(float2*)&C[row * H_DIM + c] = o;
            }
        }
    }
}

// ============================ GEMM (fp32, layer 2) ============================
template <int BM, int BN, int BK, int TM, int TN, int NT, bool RELU_A>
__global__ void __launch_bounds__(NT)
gemm_db_kernel(const float* __restrict__ A, const float* __restrict__ B,
               const float* __restrict__ bias, float* __restrict__ C,
               int M, int Nc, int K) {
    constexpr int SA = BM + 4;
    constexpr int SB = BN + 4;
    constexpr int AV = BM * BK / (4 * NT);
    constexpr int BV = BK * BN / (4 * NT);
    static_assert(AV >= 1 && BV >= 1, "tile too small");
    static_assert((BM / TM) * (BN / TN) == NT, "thread mapping");

    __shared__ float As[2][BK * SA];
    __shared__ float Bs[2][BK * SB];

    const int row0 = blockIdx.y * BM;
    const int col0 = blockIdx.x * BN;
    const int tid  = threadIdx.x;
    const int tx   = tid % (BN / TN);
    const int ty   = tid / (BN / TN);

    float4 areg[AV], breg[BV];

    auto ldg_tile = [&](int k0) {
        #pragma unroll
        for (int v = 0; v < AV; v++) {
            int q = tid + v * NT;
            int r = q / (BK / 4), kq = q % (BK / 4);
            float4 t = *(const float4*)&A[(size_t)(row0 + r) * K + k0 + kq * 4];
            if (RELU_A) {
                t.x = fmaxf(t.x, 0.f); t.y = fmaxf(t.y, 0.f);
                t.z = fmaxf(t.z, 0.f); t.w = fmaxf(t.w, 0.f);
            }
            areg[v] = t;
        }
        #pragma unroll
        for (int v = 0; v < BV; v++) {
            int q = tid + v * NT;
            int k = q / (BN / 4), cq = q % (BN / 4);
            breg[v] = *(const float4*)&B[(size_t)(k0 + k) * Nc + col0 + cq * 4];
        }
    };
    auto sts_tile = [&](int buf) {
        #pragma unroll
        for (int v = 0; v < AV; v++) {
            int q = tid + v * NT;
            int r = q / (BK / 4), kq = q % (BK / 4);
            As[buf][(kq * 4 + 0) * SA + r] = areg[v].x;
            As[buf][(kq * 4 + 1) * SA + r] = areg[v].y;
            As[buf][(kq * 4 + 2) * SA + r] = areg[v].z;
            As[buf][(kq * 4 + 3) * SA + r] = areg[v].w;
        }
        #pragma unroll
        for (int v = 0; v < BV; v++) {
            int q = tid + v * NT;
            int k = q / (BN / 4), cq = q % (BN / 4);
            *(float4*)&Bs[buf][k * SB + cq * 4] = breg[v];
        }
    };

    ull acc[TM][TN / 2];
    #pragma unroll
    for (int i = 0; i < TM; i++)
        #pragma unroll
        for (int j = 0; j < TN / 2; j++) acc[i][j] = 0ULL;

    ldg_tile(0);
    sts_tile(0);
    __syncthreads();

    const int T = K / BK;
    for (int t = 0; t < T; t++) {
        if (t + 1 < T) ldg_tile((t + 1) * BK);
        const int buf = t & 1;
        #pragma unroll
        for (int kk = 0; kk < BK; kk++) {
            float a_s[TM];
            #pragma unroll
            for (int i = 0; i < TM; i += 4) {
                float4 av = *(const float4*)&As[buf][kk * SA + ty * TM + i];
                a_s[i] = av.x; a_s[i + 1] = av.y; a_s[i + 2] = av.z; a_s[i + 3] = av.w;
            }
            ull b[TN / 2];
            #pragma unroll
            for (int j = 0; j < TN; j += 4) {
                ulonglong2 p = *(const ulonglong2*)&Bs[buf][kk * SB + tx * TN + j];
                b[j / 2] = p.x; b[j / 2 + 1] = p.y;
            }
            #pragma unroll
            for (int i = 0; i < TM; i++) {
                ull av2 = pack2(a_s[i]);
                #pragma unroll
                for (int j = 0; j < TN / 2; j++)
                    ffma2(acc[i][j], av2, b[j]);
            }
        }
        if (t + 1 < T) {
            sts_tile((t + 1) & 1);
            __syncthreads();
        }
    }

    #pragma unroll
    for (int i = 0; i < TM; i++) {
        size_t row = (size_t)(row0 + ty * TM + i);
        #pragma unroll
        for (int j = 0; j < TN / 2; j++) {
            float lo, hi;
            unpack2(acc[i][j], lo, hi);
            int c = col0 + tx * TN + j * 2;
            float2 o = make_float2(lo + __ldg(&bias[c]), hi + __ldg(&bias[c + 1]));
            *(float2*)&C[row * Nc + c] = o;
        }
    }
}

// ============================ CSR SpMM (float4 lanes) =========================
template <int F, int NT>
__global__ void __launch_bounds__(NT)
spmm_csr_kernel(const float* __restrict__ in, float* __restrict__ out) {
    constexpr int TPR = F / 4;
    constexpr int RPB = NT / TPR;
    const int sub = threadIdx.x / TPR;
    const int f4  = threadIdx.x % TPR;
    const int row = blockIdx.x * RPB + sub;
    const float4* in4 = (const float4*)in;

    int s = g_rowptr[row];
    int e = g_rowptr[row + 1];
    float4 acc = make_float4(0.f, 0.f, 0.f, 0.f);
    int j = s;
    for (; j + 4 <= e; j += 4) {
        int   c0 = g_ecol[j],     c1 = g_ecol[j + 1];
        int   c2 = g_ecol[j + 2], c3 = g_ecol[j + 3];
        float v0 = g_eval[j],     v1 = g_eval[j + 1];
        float v2 = g_eval[j + 2], v3 = g_eval[j + 3];
        float4 x0 = __ldg(&in4[(size_t)c0 * TPR + f4]);
        float4 x1 = __ldg(&in4[(size_t)c1 * TPR + f4]);
        float4 x2 = __ldg(&in4[(size_t)c2 * TPR + f4]);
        float4 x3 = __ldg(&in4[(size_t)c3 * TPR + f4]);
        acc.x = fmaf(v0, x0.x, acc.x); acc.y = fmaf(v0, x0.y, acc.y);
        acc.z = fmaf(v0, x0.z, acc.z); acc.w = fmaf(v0, x0.w, acc.w);
        acc.x = fmaf(v1, x1.x, acc.x); acc.y = fmaf(v1, x1.y, acc.y);
        acc.z = fmaf(v1, x1.z, acc.z); acc.w = fmaf(v1, x1.w, acc.w);
        acc.x = fmaf(v2, x2.x, acc.x); acc.y = fmaf(v2, x2.y, acc.y);
        acc.z = fmaf(v2, x2.z, acc.z); acc.w = fmaf(v2, x2.w, acc.w);
        acc.x = fmaf(v3, x3.x, acc.x); acc.y = fmaf(v3, x3.y, acc.y);
        acc.z = fmaf(v3, x3.z, acc.z); acc.w = fmaf(v3, x3.w, acc.w);
    }
    for (; j < e; j++) {
        float v = g_eval[j];
        float4 x = __ldg(&in4[(size_t)g_ecol[j] * TPR + f4]);
        acc.x = fmaf(v, x.x, acc.x); acc.y = fmaf(v, x.y, acc.y);
        acc.z = fmaf(v, x.z, acc.z); acc.w = fmaf(v, x.w, acc.w);
    }
    ((float4*)out)[(size_t)row * TPR + f4] = acc;
}

// ============================ Decoder =========================================
__global__ void __launch_bounds__(256)
decode_kernel(const float* __restrict__ z, float* __restrict__ out) {
    extern __shared__ float sm[];
    float* zi = sm;
    float* zj = sm + 64 * 132;

    int t = blockIdx.x;
    int bi = 0, rem = t;
    while (rem >= 64 - bi) { rem -= 64 - bi; bi++; }
    int bj = bi + rem;
    const int i0 = bi * 128, j0 = bj * 128;
    const int tid = threadIdx.x;

    for (int q = tid; q < 128 * 16; q += 256) {
        int r = q >> 4, c4 = q & 15;
        float4 a = *(const float4*)&z[(size_t)(i0 + r) * 64 + c4 * 4];
        zi[(c4 * 4 + 0) * 132 + r] = a.x;
        zi[(c4 * 4 + 1) * 132 + r] = a.y;
        zi[(c4 * 4 + 2) * 132 + r] = a.z;
        zi[(c4 * 4 + 3) * 132 + r] = a.w;
        float4 b = *(const float4*)&z[(size_t)(j0 + r) * 64 + c4 * 4];
        zj[(c4 * 4 + 0) * 132 + r] = b.x;
        zj[(c4 * 4 + 1) * 132 + r] = b.y;
        zj[(c4 * 4 + 2) * 132 + r] = b.z;
        zj[(c4 * 4 + 3) * 132 + r] = b.w;
    }
    __syncthreads();

    const int tx = tid & 15, ty = tid >> 4;
    ull acc[8][4];
    #pragma unroll
    for (int i = 0; i < 8; i++)
        #pragma unroll
        for (int j = 0; j < 4; j++) acc[i][j] = 0ULL;

    #pragma unroll 8
    for (int k = 0; k < 64; k++) {
        float4 a0 = *(const float4*)&zi[k * 132 + ty * 8];
        float4 a1 = *(const float4*)&zi[k * 132 + ty * 8 + 4];
        ulonglong2 pb0 = *(const ulonglong2*)&zj[k * 132 + tx * 8];
        ulonglong2 pb1 = *(const ulonglong2*)&zj[k * 132 + tx * 8 + 4];
        float a_s[8] = {a0.x, a0.y, a0.z, a0.w, a1.x, a1.y, a1.z, a1.w};
        ull b[4] = {pb0.x, pb0.y, pb1.x, pb1.y};
        #pragma unroll
        for (int i = 0; i < 8; i++) {
            ull av = pack2(a_s[i]);
            #pragma unroll
            for (int j = 0; j < 4; j++)
                ffma2(acc[i][j], av, b[j]);
        }
    }

    const bool mirror = (bi != bj);
    if (mirror) __syncthreads();
    float* stg = sm;

    #pragma unroll
    for (int i = 0; i < 8; i++) {
        int r = ty * 8 + i;
        size_t row = (size_t)(i0 + r);
        float s[8];
        #pragma unroll
        for (int j = 0; j < 4; j++) {
            float lo, hi;
            unpack2(acc[i][j], lo, hi);
            s[j * 2]     = fast_sigmoid(lo);
            s[j * 2 + 1] = fast_sigmoid(hi);
        }
        float4 o0 = make_float4(s[0], s[1], s[2], s[3]);
        float4 o1 = make_float4(s[4], s[5], s[6], s[7]);
        *(float4*)&out[row * N_NODES + j0 + tx * 8]     = o0;
        *(float4*)&out[row * N_NODES + j0 + tx * 8 + 4] = o1;
        if (mirror) {
            #pragma unroll
            for (int j = 0; j < 8; j++)
                stg[r * 129 + tx * 8 + j] = s[j];
        }
    }

    if (mirror) {
        __syncthreads();
        for (int idx = tid; idx < 128 * 128; idx += 256) {
            int c = idx >> 7;
            int r = idx & 127;
            out[(size_t)(j0 + c) * N_NODES + i0 + r] = stg[r * 129 + c];
        }
    }
}

// ============================ launch ==========================================
extern "C" void kernel_launch(void* const* d_in, const int* in_sizes, int n_in,
                              void* d_out, int out_size) {
    const float* x    = (const float*)d_in[0];
    const int*   rows = (const int*)  d_in[1];
    const int*   cols = (const int*)  d_in[2];
    const float* vals = (const float*)d_in[3];
    const float* W1   = (const float*)d_in[4];
    const float* b1   = (const float*)d_in[5];
    const float* W2   = (const float*)d_in[6];
    const float* b2   = (const float*)d_in[7];
    float* out = (float*)d_out;

    float *hpre, *h, *zpre;
    cudaGetSymbolAddress((void**)&hpre, g_hpre);
    cudaGetSymbolAddress((void**)&h,    g_h);
    cudaGetSymbolAddress((void**)&zpre, g_zpre);

    cudaStream_t s2;
    cudaEvent_t  eFork, eJoin;
    cudaStreamCreateWithFlags(&s2, cudaStreamNonBlocking);
    cudaEventCreateWithFlags(&eFork, cudaEventDisableTiming);
    cudaEventCreateWithFlags(&eJoin, cudaEventDisableTiming);

    // Fork: CSR build on s2, concurrent with gemm1 on the main stream.
    cudaEventRecord(eFork, 0);
    cudaStreamWaitEvent(s2, eFork, 0);
    count_kernel<<<N_EDGES / 256, 256, 0, s2>>>(rows);
    scan_kernel<<<1, 1024, 0, s2>>>();
    scatter_kernel<<<N_EDGES / 256, 256, 0, s2>>>(rows, cols, vals);
    cudaEventRecord(eJoin, s2);

    // gemm1 block-split-K: hpre = x @ W1 + b1. 512 blocks x 4 warps.
    {
        dim3 grid(H_DIM / 64, N_NODES / 64);    // 4 x 128 = 512 blocks
        gemm1_bsk_kernel<<<grid, 128>>>(x, W1, b1, hpre);
    }

    // Join: spmm1 needs both gemm1 (main) and CSR (s2).
    cudaStreamWaitEvent(0, eJoin, 0);

    // spmm1: h = A @ hpre
    spmm_csr_kernel<H_DIM, 256><<<N_NODES / 4, 256>>>(hpre, h);

    // gemm2: zpre = relu(h) @ W2 + b2 (R7 config: 16x64 tiles, 512 blocks)
    {
        dim3 grid(D_DIM / 64, N_NODES / 16);
        gemm_db_kernel<16, 64, 16, 4, 4, 64, true>
            <<<grid, 64>>>(h, W2, b2, zpre, N_NODES, D_DIM, H_DIM);
    }
    // spmm2: z = A @ zpre -> out[0 : N*D]
    spmm_csr_kernel<D_DIM, 256><<<N_NODES / 16, 256>>>(zpre, out);

    // decoder
    {
        const int smem = 2 * 64 * 132 * sizeof(float);
        cudaFuncSetAttribute(decode_kernel,
                             cudaFuncAttributeMaxDynamicSharedMemorySize, smem);
        int nblk = 64 * 65 / 2;
        decode_kernel<<<nblk, 256, smem>>>(out, out + (size_t)N_NODES * D_DIM);
    }
}

// round 12
// speedup vs baseline: 1.0672x; 1.0672x over previous
#include <cuda_runtime.h>
#include <cuda_bf16.h>
#include <cstdint>

#define N_NODES 8192
#define F_INP   512
#define H_DIM   256
#define D_DIM   64
#define N_EDGES 262144

typedef unsigned long long ull;

// ---------------- device scratch ---------------------------------------------
__device__ float g_hpre[N_NODES * H_DIM];
__device__ float g_h   [N_NODES * H_DIM];
__device__ float g_zpre[N_NODES * D_DIM];
__device__ int   g_cnt   [N_NODES];        // zero-init at load; re-zeroed by scatter
__device__ int   g_rowptr[N_NODES + 1];
__device__ int   g_fill  [N_NODES];
__device__ int   g_ecol  [N_EDGES];
__device__ float g_eval  [N_EDGES];

// ---------------- packed f32x2 helpers ---------------------------------------
__device__ __forceinline__ void ffma2(ull& acc, ull a, ull b) {
    asm("fma.rn.f32x2 %0, %1, %2, %0;" : "+l"(acc) : "l"(a), "l"(b));
}
__device__ __forceinline__ ull pack2(float v) {
    ull r;
    asm("mov.b64 %0, {%1, %1};" : "=l"(r) : "f"(v));
    return r;
}
__device__ __forceinline__ void unpack2(ull v, float& lo, float& hi) {
    asm("mov.b64 {%0, %1}, %2;" : "=f"(lo), "=f"(hi) : "l"(v));
}
__device__ __forceinline__ float fast_sigmoid(float x) {
    return __fdividef(1.0f, 1.0f + __expf(-x));
}

// ============================ CSR build =======================================
__global__ void count_kernel(const int* __restrict__ rows) {
    int e = blockIdx.x * blockDim.x + threadIdx.x;
    if (e < N_EDGES) atomicAdd(&g_cnt[rows[e]], 1);
}

__global__ void scan_kernel() {
    __shared__ int sm[1024];
    int tid  = threadIdx.x;
    int base = tid * 8;
    int v[8], pre[8];
    int s = 0;
    #pragma unroll
    for (int i = 0; i < 8; i++) { v[i] = g_cnt[base + i]; pre[i] = s; s += v[i]; }
    sm[tid] = s;
    __syncthreads();
    for (int off = 1; off < 1024; off <<= 1) {
        int t = (tid >= off) ? sm[tid - off] : 0;
        __syncthreads();
        sm[tid] += t;
        __syncthreads();
    }
    int excl = sm[tid] - s;
    #pragma unroll
    for (int i = 0; i < 8; i++) {
        int p = excl + pre[i];
        g_rowptr[base + i] = p;
        g_fill[base + i]   = p;
    }
    if (tid == 1023) g_rowptr[N_NODES] = sm[1023];
}

__global__ void scatter_kernel(const int* __restrict__ rows,
                               const int* __restrict__ cols,
                               const float* __restrict__ vals) {
    int e = blockIdx.x * blockDim.x + threadIdx.x;
    if (e < N_EDGES) {
        int pos = atomicAdd(&g_fill[rows[e]], 1);
        g_ecol[pos] = cols[e];
        g_eval[pos] = vals[e];
    }
    if (e < N_NODES) g_cnt[e] = 0;
}

// ============================ GEMM ============================================
template <int BM, int BN, int BK, int TM, int TN, int NT, bool RELU_A>
__global__ void __launch_bounds__(NT)
gemm_db_kernel(const float* __restrict__ A, const float* __restrict__ B,
               const float* __restrict__ bias, float* __restrict__ C,
               int M, int Nc, int K) {
    constexpr int SA = BM + 4;
    constexpr int SB = BN + 4;
    constexpr int AV = BM * BK / (4 * NT);
    constexpr int BV = BK * BN / (4 * NT);
    static_assert(AV >= 1 && BV >= 1, "tile too small");
    static_assert((BM / TM) * (BN / TN) == NT, "thread mapping");

    __shared__ float As[2][BK * SA];
    __shared__ float Bs[2][BK * SB];

    const int row0 = blockIdx.y * BM;
    const int col0 = blockIdx.x * BN;
    const int tid  = threadIdx.x;
    const int tx   = tid % (BN / TN);
    const int ty   = tid / (BN / TN);

    float4 areg[AV], breg[BV];

    auto ldg_tile = [&](int k0) {
        #pragma unroll
        for (int v = 0; v < AV; v++) {
            int q = tid + v * NT;
            int r = q / (BK / 4), kq = q % (BK / 4);
            float4 t = *(const float4*)&A[(size_t)(row0 + r) * K + k0 + kq * 4];
            if (RELU_A) {
                t.x = fmaxf(t.x, 0.f); t.y = fmaxf(t.y, 0.f);
                t.z = fmaxf(t.z, 0.f); t.w = fmaxf(t.w, 0.f);
            }
            areg[v] = t;
        }
        #pragma unroll
        for (int v = 0; v < BV; v++) {
            int q = tid + v * NT;
            int k = q / (BN / 4), cq = q % (BN / 4);
            breg[v] = *(const float4*)&B[(size_t)(k0 + k) * Nc + col0 + cq * 4];
        }
    };
    auto sts_tile = [&](int buf) {
        #pragma unroll
        for (int v = 0; v < AV; v++) {
            int q = tid + v * NT;
            int r = q / (BK / 4), kq = q % (BK / 4);
            As[buf][(kq * 4 + 0) * SA + r] = areg[v].x;
            As[buf][(kq * 4 + 1) * SA + r] = areg[v].y;
            As[buf][(kq * 4 + 2) * SA + r] = areg[v].z;
            As[buf][(kq * 4 + 3) * SA + r] = areg[v].w;
        }
        #pragma unroll
        for (int v = 0; v < BV; v++) {
            int q = tid + v * NT;
            int k = q / (BN / 4), cq = q % (BN / 4);
            *(float4*)&Bs[buf][k * SB + cq * 4] = breg[v];
        }
    };

    ull acc[TM][TN / 2];
    #pragma unroll
    for (int i = 0; i < TM; i++)
        #pragma unroll
        for (int j = 0; j < TN / 2; j++) acc[i][j] = 0ULL;

    ldg_tile(0);
    sts_tile(0);
    __syncthreads();

    const int T = K / BK;
    for (int t = 0; t < T; t++) {
        if (t + 1 < T) ldg_tile((t + 1) * BK);
        const int buf = t & 1;
        #pragma unroll
        for (int kk = 0; kk < BK; kk++) {
            float a_s[TM];
            #pragma unroll
            for (int i = 0; i < TM; i += 4) {
                float4 av = *(const float4*)&As[buf][kk * SA + ty * TM + i];
                a_s[i] = av.x; a_s[i + 1] = av.y; a_s[i + 2] = av.z; a_s[i + 3] = av.w;
            }
            ull b[TN / 2];
            #pragma unroll
            for (int j = 0; j < TN; j += 4) {
                ulonglong2 p = *(const ulonglong2*)&Bs[buf][kk * SB + tx * TN + j];
                b[j / 2] = p.x; b[j / 2 + 1] = p.y;
            }
            #pragma unroll
            for (int i = 0; i < TM; i++) {
                ull av2 = pack2(a_s[i]);
                #pragma unroll
                for (int j = 0; j < TN / 2; j++)
                    ffma2(acc[i][j], av2, b[j]);
            }
        }
        if (t + 1 < T) {
            sts_tile((t + 1) & 1);
            __syncthreads();
        }
    }

    #pragma unroll
    for (int i = 0; i < TM; i++) {
        size_t row = (size_t)(row0 + ty * TM + i);
        #pragma unroll
        for (int j = 0; j < TN / 2; j++) {
            float lo, hi;
            unpack2(acc[i][j], lo, hi);
            int c = col0 + tx * TN + j * 2;
            float2 o = make_float2(lo + __ldg(&bias[c]), hi + __ldg(&bias[c + 1]));
            *(float2*)&C[row * Nc + c] = o;
        }
    }
}

// ============================ CSR SpMM (float4 lanes) =========================
template <int F, int NT>
__global__ void __launch_bounds__(NT)
spmm_csr_kernel(const float* __restrict__ in, float* __restrict__ out) {
    constexpr int TPR = F / 4;
    constexpr int RPB = NT / TPR;
    const int sub = threadIdx.x / TPR;
    const int f4  = threadIdx.x % TPR;
    const int row = blockIdx.x * RPB + sub;
    const float4* in4 = (const float4*)in;

    int s = g_rowptr[row];
    int e = g_rowptr[row + 1];
    float4 acc = make_float4(0.f, 0.f, 0.f, 0.f);
    int j = s;
    for (; j + 4 <= e; j += 4) {
        int   c0 = g_ecol[j],     c1 = g_ecol[j + 1];
        int   c2 = g_ecol[j + 2], c3 = g_ecol[j + 3];
        float v0 = g_eval[j],     v1 = g_eval[j + 1];
        float v2 = g_eval[j + 2], v3 = g_eval[j + 3];
        float4 x0 = __ldg(&in4[(size_t)c0 * TPR + f4]);
        float4 x1 = __ldg(&in4[(size_t)c1 * TPR + f4]);
        float4 x2 = __ldg(&in4[(size_t)c2 * TPR + f4]);
        float4 x3 = __ldg(&in4[(size_t)c3 * TPR + f4]);
        acc.x = fmaf(v0, x0.x, acc.x); acc.y = fmaf(v0, x0.y, acc.y);
        acc.z = fmaf(v0, x0.z, acc.z); acc.w = fmaf(v0, x0.w, acc.w);
        acc.x = fmaf(v1, x1.x, acc.x); acc.y = fmaf(v1, x1.y, acc.y);
        acc.z = fmaf(v1, x1.z, acc.z); acc.w = fmaf(v1, x1.w, acc.w);
        acc.x = fmaf(v2, x2.x, acc.x); acc.y = fmaf(v2, x2.y, acc.y);
        acc.z = fmaf(v2, x2.z, acc.z); acc.w = fmaf(v2, x2.w, acc.w);
        acc.x = fmaf(v3, x3.x, acc.x); acc.y = fmaf(v3, x3.y, acc.y);
        acc.z = fmaf(v3, x3.z, acc.z); acc.w = fmaf(v3, x3.w, acc.w);
    }
    for (; j < e; j++) {
        float v = g_eval[j];
        float4 x = __ldg(&in4[(size_t)g_ecol[j] * TPR + f4]);
        acc.x = fmaf(v, x.x, acc.x); acc.y = fmaf(v, x.y, acc.y);
        acc.z = fmaf(v, x.z, acc.z); acc.w = fmaf(v, x.w, acc.w);
    }
    ((float4*)out)[(size_t)row * TPR + f4] = acc;
}

// ============================ Decoder =========================================
// sigmoid(z z^T) upper-triangle 128x128 tiles + mirror.
// __launch_bounds__(256, 2): cap regs at 128 so 2 blocks/SM are resident
// (8x4 ull acc kernels otherwise compile to ~160 regs -> 1 block/SM).
__global__ void __launch_bounds__(256, 2)
decode_kernel(const float* __restrict__ z, float* __restrict__ out) {
    extern __shared__ float sm[];
    float* zi = sm;                  // [64][132]
    float* zj = sm + 64 * 132;       // [64][132]

    int t = blockIdx.x;
    int bi = 0, rem = t;
    while (rem >= 64 - bi) { rem -= 64 - bi; bi++; }
    int bj = bi + rem;
    const int i0 = bi * 128, j0 = bj * 128;
    const int tid = threadIdx.x;

    for (int q = tid; q < 128 * 16; q += 256) {
        int r = q >> 4, c4 = q & 15;
        float4 a = *(const float4*)&z[(size_t)(i0 + r) * 64 + c4 * 4];
        zi[(c4 * 4 + 0) * 132 + r] = a.x;
        zi[(c4 * 4 + 1) * 132 + r] = a.y;
        zi[(c4 * 4 + 2) * 132 + r] = a.z;
        zi[(c4 * 4 + 3) * 132 + r] = a.w;
        float4 b = *(const float4*)&z[(size_t)(j0 + r) * 64 + c4 * 4];
        zj[(c4 * 4 + 0) * 132 + r] = b.x;
        zj[(c4 * 4 + 1) * 132 + r] = b.y;
        zj[(c4 * 4 + 2) * 132 + r] = b.z;
        zj[(c4 * 4 + 3) * 132 + r] = b.w;
    }
    __syncthreads();

    const int tx = tid & 15, ty = tid >> 4;
    ull acc[8][4];
    #pragma unroll
    for (int i = 0; i < 8; i++)
        #pragma unroll
        for (int j = 0; j < 4; j++) acc[i][j] = 0ULL;

    #pragma unroll 8
    for (int k = 0; k < 64; k++) {
        float4 a0 = *(const float4*)&zi[k * 132 + ty * 8];
        float4 a1 = *(const float4*)&zi[k * 132 + ty * 8 + 4];
        ulonglong2 pb0 = *(const ulonglong2*)&zj[k * 132 + tx * 8];
        ulonglong2 pb1 = *(const ulonglong2*)&zj[k * 132 + tx * 8 + 4];
        float a_s[8] = {a0.x, a0.y, a0.z, a0.w, a1.x, a1.y, a1.z, a1.w};
        ull b[4] = {pb0.x, pb0.y, pb1.x, pb1.y};
        #pragma unroll
        for (int i = 0; i < 8; i++) {
            ull av = pack2(a_s[i]);
            #pragma unroll
            for (int j = 0; j < 4; j++)
                ffma2(acc[i][j], av, b[j]);
        }
    }

    const bool mirror = (bi != bj);
    if (mirror) __syncthreads();
    float* stg = sm;

    #pragma unroll
    for (int i = 0; i < 8; i++) {
        int r = ty * 8 + i;
        size_t row = (size_t)(i0 + r);
        float s[8];
        #pragma unroll
        for (int j = 0; j < 4; j++) {
            float lo, hi;
            unpack2(acc[i][j], lo, hi);
            s[j * 2]     = fast_sigmoid(lo);
            s[j * 2 + 1] = fast_sigmoid(hi);
        }
        float4 o0 = make_float4(s[0], s[1], s[2], s[3]);
        float4 o1 = make_float4(s[4], s[5], s[6], s[7]);
        *(float4*)&out[row * N_NODES + j0 + tx * 8]     = o0;
        *(float4*)&out[row * N_NODES + j0 + tx * 8 + 4] = o1;
        if (mirror) {
            #pragma unroll
            for (int j = 0; j < 8; j++)
                stg[r * 129 + tx * 8 + j] = s[j];
        }
    }

    if (mirror) {
        __syncthreads();
        for (int idx = tid; idx < 128 * 128; idx += 256) {
            int c = idx >> 7;
            int r = idx & 127;
            out[(size_t)(j0 + c) * N_NODES + i0 + r] = stg[r * 129 + c];
        }
    }
}

// ============================ launch ==========================================
extern "C" void kernel_launch(void* const* d_in, const int* in_sizes, int n_in,
                              void* d_out, int out_size) {
    const float* x    = (const float*)d_in[0];
    const int*   rows = (const int*)  d_in[1];
    const int*   cols = (const int*)  d_in[2];
    const float* vals = (const float*)d_in[3];
    const float* W1   = (const float*)d_in[4];
    const float* b1   = (const float*)d_in[5];
    const float* W2   = (const float*)d_in[6];
    const float* b2   = (const float*)d_in[7];
    float* out = (float*)d_out;

    float *hpre, *h, *zpre;
    cudaGetSymbolAddress((void**)&hpre, g_hpre);
    cudaGetSymbolAddress((void**)&h,    g_h);
    cudaGetSymbolAddress((void**)&zpre, g_zpre);

    cudaStream_t s2;
    cudaEvent_t  eFork, eJoin;
    cudaStreamCreateWithFlags(&s2, cudaStreamNonBlocking);
    cudaEventCreateWithFlags(&eFork, cudaEventDisableTiming);
    cudaEventCreateWithFlags(&eJoin, cudaEventDisableTiming);

    // Fork: CSR build on s2, concurrent with gemm1 on the main stream.
    cudaEventRecord(eFork, 0);
    cudaStreamWaitEvent(s2, eFork, 0);
    count_kernel<<<N_EDGES / 256, 256, 0, s2>>>(rows);
    scan_kernel<<<1, 1024, 0, s2>>>();
    scatter_kernel<<<N_EDGES / 256, 256, 0, s2>>>(rows, cols, vals);
    cudaEventRecord(eJoin, s2);

    // gemm1 (R7 config): hpre = x @ W1 + b1, 64x32-grain grid of 1024 blocks.
    {
        dim3 grid(H_DIM / 32, N_NODES / 64);     // 8 x 128 = 1024 blocks
        gemm_db_kernel<64, 32, 16, 8, 4, 64, false>
            <<<grid, 64>>>(x, W1, b1, hpre, N_NODES, H_DIM, F_INP);
    }

    // Join: spmm1 needs both gemm1 (main) and CSR (s2).
    cudaStreamWaitEvent(0, eJoin, 0);

    // spmm1: h = A @ hpre
    spmm_csr_kernel<H_DIM, 256><<<N_NODES / 4, 256>>>(hpre, h);

    // gemm2 (R7 config): zpre = relu(h) @ W2 + b2. 16x64 tiles -> 512 blocks.
    {
        dim3 grid(D_DIM / 64, N_NODES / 16);
        gemm_db_kernel<16, 64, 16, 4, 4, 64, true>
            <<<grid, 64>>>(h, W2, b2, zpre, N_NODES, D_DIM, H_DIM);
    }
    // spmm2: z = A @ zpre -> out[0 : N*D]
    spmm_csr_kernel<D_DIM, 256><<<N_NODES / 16, 256>>>(zpre, out);

    // decoder (now guaranteed 2 blocks/SM)
    {
        const int smem = 2 * 64 * 132 * sizeof(float);
        cudaFuncSetAttribute(decode_kernel,
                             cudaFuncAttributeMaxDynamicSharedMemorySize, smem);
        int nblk = 64 * 65 / 2;
        decode_kernel<<<nblk, 256, smem>>>(out, out + (size_t)N_NODES * D_DIM);
    }
}